// round 17
// baseline (speedup 1.0000x reference)
#include <cuda_runtime.h>

// MaskedWeight: B=256, DIM=16, H_IN=H_OUT=32, IN_F=OUT_F=512
// Persistent single-wave kernel: grid = 592 = 148 SMs x 4 CTAs, 256 thr.
// Work = 4096 slices (16 per sample); CTA k owns a CONTIGUOUS run
// (k<544: 7 slices from 7k; else 6 from 3808+6(k-544)) -> 1.2% imbalance,
// x/lgc reloaded only on sample change (<=3 per CTA).
// Per slice: each warp does 2 balanced row pairs (rb, 15-rb), 2-deep load
// pipeline, max-free logsumexp. Frobenius partial per (slice,warp) slot.
// Sample finalize: atomicAdd(run length) reaching 16 -> fixed-order sum of
// 128 partials, write outputs, reset counter (graph-replay safe).
// No spin loops, no inter-CTA waits: forward progress is unconditional.

#define NB 256
#define OUTF 512
#define INF 512
#define SLICES 16
#define TOTAL_SLICES (NB * SLICES)   // 4096
#define GRID 592

__device__ float g_yraw[NB * OUTF];
__device__ float g_lse[NB * OUTF];
__device__ float g_f2w[TOTAL_SLICES * 8];   // per (slice, warp)
__device__ unsigned int g_cnt[NB];          // zero-init; finalizer resets to 0

__global__ __launch_bounds__(256, 4)
void mw_persist(const float* __restrict__ inputs,     // [B, 512]
                const float* __restrict__ hyper_w,    // [B, 512, 512]
                const float* __restrict__ hyper_b,    // [B, 512]
                const float* __restrict__ lgc,        // [B, 16, 32, 1]
                const float* __restrict__ sfp,        // [1]
                float* __restrict__ out)              // [outputs | log_det]
{
    const int cta = blockIdx.x;
    int start, cnt;
    if (cta < 544) { start = 7 * cta;                cnt = 7; }
    else           { start = 3808 + 6 * (cta - 544); cnt = 6; }

    const int tid  = threadIdx.x;
    const int warp = tid >> 5;
    const int lane = tid & 31;

    __shared__ __align__(16) float x_s[INF];
    __shared__ float lgc_s[512];
    __shared__ float F2sh;
    __shared__ int amLast;

    int prev_b   = -1;
    int runStart = 0;

    for (int it = 0; it < cnt; ++it) {
        const int slice = start + it;
        const int b = slice >> 4;
        const int s = slice & 15;

        if (b != prev_b) {
            // Previous sample's run ended with __syncthreads() in the
            // run-end block, so x_s/lgc_s reads completed before overwrite.
            x_s[tid]         = inputs[b * INF + tid];
            x_s[tid + 256]   = inputs[b * INF + tid + 256];
            lgc_s[tid]       = lgc[b * 512 + tid];
            lgc_s[tid + 256] = lgc[b * 512 + tid + 256];
            __syncthreads();
            prev_b = b;
            runStart = it;
        }

        const float*  hw = hyper_w + (size_t)b * (OUTF * INF);
        const float4* x4 = reinterpret_cast<const float4*>(x_s);
        const int g    = (s << 3) + warp;   // 0..127
        const int colA = g & 31;
        const int rb0  = g >> 5;            // 0..3

        float f2 = 0.0f;
        float4 v0[4], v1[4];
        float dA0, dB0, dA1, dB1;

        // Load one pair's data (4 predicated LDG.128 + 2 scalar LDG).
#define LOADP(RBA, V, DA, DB) do {                                            \
        const int rbA = (RBA);                                                \
        const int rbB = 15 - rbA;                                             \
        const float* rowA = hw + (size_t)((rbA << 5) + colA) * INF;           \
        const float* rowB = hw + (size_t)((rbB << 5) + colA) * INF;           \
        const int n4a = rbA << 3;                                             \
        _Pragma("unroll")                                                     \
        for (int j = 0; j < 4; j++) {                                         \
            const int i4 = lane + 32 * j;                                     \
            const float* p = (i4 < n4a) ? rowA : rowB;                        \
            const int idx  = (i4 < n4a) ? i4 : (i4 - n4a);                    \
            float4 t = make_float4(0.f, 0.f, 0.f, 0.f);                       \
            if (i4 < 120) t = reinterpret_cast<const float4*>(p)[idx];        \
            V[j] = t;                                                         \
        }                                                                     \
        DA = rowA[(rbA << 5) + lane];                                         \
        DB = rowB[(rbB << 5) + lane];                                         \
    } while (0)

        // Consume one pair: FMAs + inline interleaved reductions + store.
#define PROCP(RBA, V, DA, DB) do {                                            \
        const int rbA = (RBA);                                                \
        const int rbB = 15 - rbA;                                             \
        const int n4a = rbA << 3;                                             \
        float ya = 0.0f, yb = 0.0f;                                           \
        _Pragma("unroll")                                                     \
        for (int j = 0; j < 4; j++) {                                         \
            const int i4 = lane + 32 * j;                                     \
            const bool inA = (i4 < n4a);                                      \
            const int idx  = inA ? i4 : (i4 - n4a);                           \
            const float4 xv = x4[idx];                                        \
            const float4 v  = V[j];                                           \
            float dot = v.x * xv.x;                                           \
            dot = fmaf(v.y, xv.y, dot);                                       \
            dot = fmaf(v.z, xv.z, dot);                                       \
            dot = fmaf(v.w, xv.w, dot);                                       \
            f2 = fmaf(v.x, v.x, f2);                                          \
            f2 = fmaf(v.y, v.y, f2);                                          \
            f2 = fmaf(v.z, v.z, f2);                                          \
            f2 = fmaf(v.w, v.w, f2);                                          \
            if (inA) ya += dot; else yb += dot;                               \
        }                                                                     \
        const int dAc = rbA << 5, dBc = rbB << 5;                             \
        const float eA = __expf(DA), eB = __expf(DB);                         \
        ya = fmaf(eA, x_s[dAc + lane], ya);                                   \
        yb = fmaf(eB, x_s[dBc + lane], yb);                                   \
        f2 = fmaf(eA, eA, f2);                                                \
        f2 = fmaf(eB, eB, f2);                                                \
        /* max-free logsumexp: values O(1), fp32-safe */                      \
        float sA = __expf(DA + lgc_s[dAc + lane]);                            \
        float sB = __expf(DB + lgc_s[dBc + lane]);                            \
        _Pragma("unroll")                                                     \
        for (int sh = 16; sh; sh >>= 1) {                                     \
            ya += __shfl_xor_sync(0xffffffffu, ya, sh);                       \
            yb += __shfl_xor_sync(0xffffffffu, yb, sh);                       \
            sA += __shfl_xor_sync(0xffffffffu, sA, sh);                       \
            sB += __shfl_xor_sync(0xffffffffu, sB, sh);                       \
        }                                                                     \
        if (lane == 0) {                                                      \
            const int oA = dAc + colA;                                        \
            g_yraw[b * OUTF + oA] = ya;                                       \
            g_lse [b * OUTF + oA] = __logf(sA);                               \
        } else if (lane == 1) {                                               \
            const int oB = dBc + colA;                                        \
            g_yraw[b * OUTF + oB] = yb;                                       \
            g_lse [b * OUTF + oB] = __logf(sB);                               \
        }                                                                     \
    } while (0)

        LOADP(rb0,     v0, dA0, dB0);
        LOADP(rb0 + 4, v1, dA1, dB1);
        PROCP(rb0,     v0, dA0, dB0);
        PROCP(rb0 + 4, v1, dA1, dB1);

#undef LOADP
#undef PROCP

        // per-(slice,warp) Frobenius partial — no CTA sync needed
        #pragma unroll
        for (int sh = 16; sh; sh >>= 1) f2 += __shfl_xor_sync(0xffffffffu, f2, sh);
        if (lane == 0) g_f2w[slice * 8 + warp] = f2;

        // ---- run-end: count this CTA's contribution to sample b ----
        const bool runEnd = (it == cnt - 1) || (((slice + 1) >> 4) != b);
        if (runEnd) {
            __threadfence();
            __syncthreads();
            if (tid == 0) {
                const unsigned int rl = (unsigned int)(it - runStart + 1);
                const unsigned int old = atomicAdd(&g_cnt[b], rl);
                amLast = (old + rl == SLICES) ? 1 : 0;
            }
            __syncthreads();
            if (amLast) {
                __threadfence();
                if (warp == 0) {
                    float t = 0.0f;
                    #pragma unroll
                    for (int i = 0; i < 4; i++)
                        t += g_f2w[b * 128 + lane + 32 * i];   // fixed order
                    #pragma unroll
                    for (int sh = 16; sh; sh >>= 1)
                        t += __shfl_xor_sync(0xffffffffu, t, sh);  // fixed tree
                    if (lane == 0) F2sh = t;
                }
                __syncthreads();
                const float F2   = F2sh;
                const float sf   = sfp[0];
                const float inv  = __expf(sf) * rsqrtf(F2);
                const float base = sf - 0.5f * __logf(F2);
                #pragma unroll
                for (int r = 0; r < 2; r++) {
                    const int o = tid + 256 * r;
                    out[b * OUTF + o] =
                        fmaf(g_yraw[b * OUTF + o], inv, hyper_b[b * OUTF + o]);
                    out[NB * OUTF + b * 512 + o] = base + g_lse[b * 512 + o];
                }
                if (tid == 0) g_cnt[b] = 0;   // reset for next graph replay
                __syncthreads();
            }
        }
    }
}

extern "C" void kernel_launch(void* const* d_in, const int* in_sizes, int n_in,
                              void* d_out, int out_size) {
    const float* inputs  = (const float*)d_in[0];
    const float* hyper_w = (const float*)d_in[1];
    const float* hyper_b = (const float*)d_in[2];
    const float* lgc     = (const float*)d_in[3];
    const float* sf      = (const float*)d_in[4];
    mw_persist<<<GRID, 256>>>(inputs, hyper_w, hyper_b, lgc, sf, (float*)d_out);
}